// round 5
// baseline (speedup 1.0000x reference)
#include <cuda_runtime.h>
#include <cuda_bf16.h>
#include <cstdint>

// ---------------- problem dims (fixed by dataset) ----------------
#define T_STEPS 512
#define BATCH   128
#define SDIM    1024
#define ODIM    256
#define JDIM    (SDIM + ODIM)   // 1280

// ---------------- tiling ----------------
#define NB 4                 // batch tiles (independent recurrence groups)
#define NJ 32                // j tiles
#define BT 32                // batch rows per CTA   (128/NB)
#define JT 40                // j cols per CTA       (1280/NJ)
#define NCTAS (NB * NJ)      // 128 CTAs, one per SM, all co-resident
#define NTHREADS 256
#define NWARPS 8
#define KSLICE 128           // K slice per warp (split-K over 8 warps)
#define CLUSTER 4            // multicast group (same btile; 32 % 4 == 0)
#define ROWS_PER_CTA (BT / CLUSTER)   // 8 G-rows loaded+multicast per CTA
#define PAD 8                // bf16 pad per smem row (16B)
#define GSTRIDE (SDIM + PAD) // 1032 halves per smem row
#define ROW_BYTES (SDIM * 2) // 2048 contiguous bytes per G row in gmem
#define EHALF (16 * JT)      // 640 elements per row-half

// smem layout (bytes)
#define SG_BYTES (BT * GSTRIDE * 2)            // 66048
#define SP_BYTES (NWARPS * BT * JT * 4)        // 40960
#define SMEM_TOTAL (SG_BYTES + SP_BYTES + 16)  // + two mbarriers

// ---------------- device globals (scratch; no allocation allowed) ----------------
__device__ __align__(16) __nv_bfloat16 g_W[(size_t)JDIM * SDIM];      // concat(w_r, w_o), bf16
__device__ __align__(16) __nv_bfloat16 g_G[2][(size_t)BATCH * SDIM];  // tanh(h), double-buffered
__device__ unsigned g_slots0[NB * 32];  // per-CTA arrival: G rows 0-15 stored + half0 reads done
__device__ unsigned g_slots1[NB * 32];  // per-CTA arrival: G rows 16-31 stored + half1 reads done

// ---------------- helpers ----------------
__device__ __forceinline__ unsigned ld_acq(const unsigned* p) {
    unsigned v;
    asm volatile("ld.acquire.gpu.global.u32 %0, [%1];" : "=r"(v) : "l"(p));
    return v;
}
__device__ __forceinline__ void st_rel(unsigned* p, unsigned v) {
    asm volatile("st.release.gpu.global.u32 [%0], %1;" :: "l"(p), "r"(v) : "memory");
}
__device__ __forceinline__ float tanh_fast(float v) {
    float r;
    asm("tanh.approx.f32 %0, %1;" : "=f"(r) : "f"(v));
    return r;
}
__device__ __forceinline__ void mma16816(float c[4], const unsigned a[4],
                                         unsigned b0, unsigned b1) {
    asm volatile(
        "mma.sync.aligned.m16n8k16.row.col.f32.bf16.bf16.f32 "
        "{%0,%1,%2,%3}, {%4,%5,%6,%7}, {%8,%9}, {%0,%1,%2,%3};\n"
        : "+f"(c[0]), "+f"(c[1]), "+f"(c[2]), "+f"(c[3])
        : "r"(a[0]), "r"(a[1]), "r"(a[2]), "r"(a[3]), "r"(b0), "r"(b1));
}
__device__ __forceinline__ void ldsm_x4(unsigned a[4], uint32_t addr) {
    asm volatile("ldmatrix.sync.aligned.m8n8.x4.shared.b16 {%0,%1,%2,%3}, [%4];"
                 : "=r"(a[0]), "=r"(a[1]), "=r"(a[2]), "=r"(a[3]) : "r"(addr));
}
__device__ __forceinline__ void mbar_wait(uint32_t mbar, unsigned parity) {
    asm volatile(
        "{\n\t"
        ".reg .pred P;\n\t"
        "WL_%=:\n\t"
        "mbarrier.try_wait.parity.acquire.cta.shared::cta.b64 P, [%0], %1, 0x989680;\n\t"
        "@P bra.uni WD_%=;\n\t"
        "bra.uni WL_%=;\n\t"
        "WD_%=:\n\t"
        "}" :: "r"(mbar), "r"(parity) : "memory");
}

// ---------------- init: bf16 weights + G0 = tanh(h_init), reset barrier slots ----------------
__global__ void trnn_init(const float* __restrict__ w_r, const float* __restrict__ w_o,
                          const float* __restrict__ h_init) {
    size_t stride = (size_t)gridDim.x * blockDim.x;
    size_t i0 = (size_t)blockIdx.x * blockDim.x + threadIdx.x;
    const size_t WR_N = (size_t)SDIM * SDIM;
    const size_t W_N  = (size_t)JDIM * SDIM;
    for (size_t i = i0; i < W_N; i += stride) {
        float v = (i < WR_N) ? w_r[i] : w_o[i - WR_N];
        g_W[i] = __float2bfloat16(v);
    }
    for (size_t i = i0; i < (size_t)BATCH * SDIM; i += stride) {
        g_G[0][i] = __float2bfloat16(tanhf(h_init[i]));
    }
    if (i0 < NB * 32) { g_slots0[i0] = 0u; g_slots1[i0] = 0u; }
}

// ---------------- persistent kernel: half-staggered pipeline ----------------
__global__ void __launch_bounds__(NTHREADS, 1) __cluster_dims__(CLUSTER, 1, 1)
trnn_persistent(const float* __restrict__ x, const float* __restrict__ h_init,
                const float* __restrict__ b_r, const float* __restrict__ b_o,
                float* __restrict__ out) {
    extern __shared__ char smem[];
    __nv_bfloat16* sG = (__nv_bfloat16*)smem;
    float* sP = (float*)(smem + SG_BYTES);
    uint32_t mbar0 = (uint32_t)__cvta_generic_to_shared(smem + SG_BYTES + SP_BYTES);
    uint32_t mbar1 = mbar0 + 8;

    const int tid  = threadIdx.x;
    const int warp = tid >> 5;
    const int lane = tid & 31;
    const int grp  = lane >> 2;   // 0..7
    const int tig  = lane & 3;    // 0..3
    const int btile = blockIdx.x >> 5;  // /NJ
    const int jtile = blockIdx.x & 31;  // %NJ
    const int rank  = blockIdx.x & (CLUSTER - 1);
    const int b0 = btile * BT;
    const int j0 = jtile * JT;
    const int kw = warp * KSLICE;

    // rank 0,1 fill rows 0-15 (gated by slots0); rank 2,3 fill rows 16-31 (slots1)
    unsigned* my_slots = (rank < 2) ? &g_slots0[btile * 32] : &g_slots1[btile * 32];
    unsigned* rel0 = &g_slots0[btile * 32 + jtile];
    unsigned* rel1 = &g_slots1[btile * 32 + jtile];
    const uint32_t my_mbar = (rank < 2) ? mbar0 : mbar1;

    if (tid == 0) {
        asm volatile("mbarrier.init.shared.b64 [%0], 1;" :: "r"(mbar0) : "memory");
        asm volatile("mbarrier.init.shared.b64 [%0], 1;" :: "r"(mbar1) : "memory");
    }
    __syncthreads();
    asm volatile("barrier.cluster.arrive.aligned;" ::: "memory");
    asm volatile("barrier.cluster.wait.aligned;"   ::: "memory");

    // --- per-thread persistent epilogue state, per half: e = d*256 + tid (< 640) ---
    // half h covers rows h*16 + e/40, col e%40
    int   ejh[2][3];    // global j (or -1 if slot unused)
    int   erow[2][3];   // global batch row
    float hr[2][3];     // resident h value (h columns)
    float bv[2][3];     // bias
    #pragma unroll
    for (int h = 0; h < 2; ++h) {
        #pragma unroll
        for (int d = 0; d < 3; ++d) {
            int e = d * NTHREADS + tid;
            if (e < EHALF) {
                int r = h * 16 + e / JT;
                int j = j0 + (e % JT);
                ejh[h][d] = j; erow[h][d] = b0 + r;
                if (j < SDIM) {
                    hr[h][d] = h_init[(size_t)(b0 + r) * SDIM + j];
                    bv[h][d] = b_r[j];
                } else {
                    hr[h][d] = 0.f;
                    bv[h][d] = b_o[j - SDIM];
                }
            } else {
                ejh[h][d] = -1; erow[h][d] = 0; hr[h][d] = 0.f; bv[h][d] = 0.f;
            }
        }
    }

    // --- W fragments: persistent in registers across all steps (80 regs/thread) ---
    unsigned Breg[8][5][2];
    #pragma unroll
    for (int ks = 0; ks < 8; ++ks) {
        #pragma unroll
        for (int ni = 0; ni < 5; ++ni) {
            int jr = ni * 8 + grp;
            const unsigned* wp = (const unsigned*)(g_W + (size_t)(j0 + jr) * SDIM + kw + ks * 16);
            Breg[ks][ni][0] = wp[tig];
            Breg[ks][ni][1] = wp[4 + tig];
        }
    }
    __syncthreads();

    // --- ldmatrix per-lane base addresses (rows 0-15 / 16-31, lo/hi k-half) ---
    const uint32_t sGb = (uint32_t)__cvta_generic_to_shared(sG);
    const int rl = lane & 15;
    const int khalf = (lane & 16) ? 8 : 0;
    const uint32_t aBase0 = sGb + (uint32_t)((rl * GSTRIDE + kw + khalf) * 2);
    const uint32_t aBase1 = aBase0 + (uint32_t)(16 * GSTRIDE * 2);

    for (int it = 0; it <= T_STEPS; ++it) {
        const unsigned parity = (unsigned)(it & 1);

        // --- expect_tx for this step's two half-tiles (local, previous phases done) ---
        if (tid == 0) {
            asm volatile("mbarrier.arrive.expect_tx.shared.b64 _, [%0], %1;"
                         :: "r"(mbar0), "r"(16 * ROW_BYTES) : "memory");
            asm volatile("mbarrier.arrive.expect_tx.shared.b64 _, [%0], %1;"
                         :: "r"(mbar1), "r"(16 * ROW_BYTES) : "memory");
        }

        // --- x prefetch (independent of G; off critical path) ---
        float xr[2][3];
        if (it >= 1) {
            #pragma unroll
            for (int h = 0; h < 2; ++h)
                #pragma unroll
                for (int d = 0; d < 3; ++d)
                    if (ejh[h][d] >= SDIM) {
                        size_t oi = ((size_t)(it - 1) * BATCH + erow[h][d]) * ODIM
                                    + (ejh[h][d] - SDIM);
                        xr[h][d] = __ldcs(x + oi);
                    }
        }

        // --- poll only the slot-set gating THIS rank's rows; warp0 only ---
        if (it > 0 && warp == 0) {
            const unsigned phase = (unsigned)it;
            for (;;) {
                unsigned v = ld_acq(&my_slots[lane]);   // 32 coalesced slots
                if (__all_sync(0xffffffffu, v >= phase)) break;
            }
        }

        // --- issue this rank's 8 multicast row-copies (tid0, right after its poll) ---
        if (tid == 0) {
            const __nv_bfloat16* Gc = g_G[it & 1];
            asm volatile("fence.proxy.async;" ::: "memory");
            #pragma unroll
            for (int rr = 0; rr < ROWS_PER_CTA; ++rr) {
                int r = rank * ROWS_PER_CTA + rr;
                const void* src = (const void*)(Gc + (size_t)(b0 + r) * SDIM);
                uint32_t dst = (uint32_t)__cvta_generic_to_shared(sG + r * GSTRIDE);
                asm volatile(
                    "cp.async.bulk.shared::cluster.global.mbarrier::complete_tx::bytes"
                    ".multicast::cluster [%0], [%1], %2, [%3], %4;"
                    :: "r"(dst), "l"(src), "r"(ROW_BYTES), "r"(my_mbar),
                       "h"((unsigned short)((1u << CLUSTER) - 1u))
                    : "memory");
            }
        }

        float yv[2][3];
        __nv_bfloat16* Gn = g_G[(it + 1) & 1];

        // ================= half 0: rows 0-15 =================
        {
            float acc[5][4];
            #pragma unroll
            for (int ni = 0; ni < 5; ++ni)
                #pragma unroll
                for (int q = 0; q < 4; ++q) acc[ni][q] = 0.f;

            mbar_wait(mbar0, parity);
            #pragma unroll
            for (int ks = 0; ks < 8; ++ks) {
                unsigned a[4];
                ldsm_x4(a, aBase0 + ks * 32);
                #pragma unroll
                for (int ni = 0; ni < 5; ++ni)
                    mma16816(acc[ni], a, Breg[ks][ni][0], Breg[ks][ni][1]);
            }
            // partials rows 0-15
            float* p = sP + warp * (BT * JT);
            #pragma unroll
            for (int ni = 0; ni < 5; ++ni) {
                int cc = ni * 8 + tig * 2;
                *(float2*)&p[grp * JT + cc]       = make_float2(acc[ni][0], acc[ni][1]);
                *(float2*)&p[(grp + 8) * JT + cc] = make_float2(acc[ni][2], acc[ni][3]);
            }
            __syncthreads();   // barA: all half0 partials written, half0 sG reads done

            // reduce + h update + G store for rows 0-15
            #pragma unroll
            for (int d = 0; d < 3; ++d) {
                int e = d * NTHREADS + tid;
                if (e < EHALF) {
                    float y = sP[e];
                    #pragma unroll
                    for (int w = 1; w < NWARPS; ++w) y += sP[w * (BT * JT) + e];
                    yv[0][d] = y;
                    if (ejh[0][d] < SDIM) {
                        float hv = 0.75f * hr[0][d] + 0.25f * (y + bv[0][d]);
                        hr[0][d] = hv;
                        Gn[(size_t)erow[0][d] * SDIM + ejh[0][d]] =
                            __float2bfloat16(tanh_fast(hv));
                    }
                }
            }
            __syncthreads();   // barC: all rows-0-15 G stores done
            if (tid == 0) st_rel(rel0, (unsigned)(it + 1));
        }

        // ================= half 1: rows 16-31 =================
        {
            float acc[5][4];
            #pragma unroll
            for (int ni = 0; ni < 5; ++ni)
                #pragma unroll
                for (int q = 0; q < 4; ++q) acc[ni][q] = 0.f;

            mbar_wait(mbar1, parity);
            #pragma unroll
            for (int ks = 0; ks < 8; ++ks) {
                unsigned a[4];
                ldsm_x4(a, aBase1 + ks * 32);
                #pragma unroll
                for (int ni = 0; ni < 5; ++ni)
                    mma16816(acc[ni], a, Breg[ks][ni][0], Breg[ks][ni][1]);
            }
            // partials rows 16-31 (disjoint sP region)
            float* p = sP + warp * (BT * JT);
            #pragma unroll
            for (int ni = 0; ni < 5; ++ni) {
                int cc = ni * 8 + tig * 2;
                *(float2*)&p[(16 + grp) * JT + cc] = make_float2(acc[ni][0], acc[ni][1]);
                *(float2*)&p[(24 + grp) * JT + cc] = make_float2(acc[ni][2], acc[ni][3]);
            }
            __syncthreads();   // barB

            #pragma unroll
            for (int d = 0; d < 3; ++d) {
                int e = d * NTHREADS + tid;
                if (e < EHALF) {
                    int ee = EHALF + e;
                    float y = sP[ee];
                    #pragma unroll
                    for (int w = 1; w < NWARPS; ++w) y += sP[w * (BT * JT) + ee];
                    yv[1][d] = y;
                    if (ejh[1][d] < SDIM) {
                        float hv = 0.75f * hr[1][d] + 0.25f * (y + bv[1][d]);
                        hr[1][d] = hv;
                        Gn[(size_t)erow[1][d] * SDIM + ejh[1][d]] =
                            __float2bfloat16(tanh_fast(hv));
                    }
                }
            }
            __syncthreads();   // barD
            if (tid == 0) st_rel(rel1, (unsigned)(it + 1));
        }

        // --- outputs (off the critical path) ---
        if (it >= 1) {
            #pragma unroll
            for (int h = 0; h < 2; ++h)
                #pragma unroll
                for (int d = 0; d < 3; ++d)
                    if (ejh[h][d] >= SDIM) {
                        size_t oi = ((size_t)(it - 1) * BATCH + erow[h][d]) * ODIM
                                    + (ejh[h][d] - SDIM);
                        out[oi] = yv[h][d] + bv[h][d] - xr[h][d];
                    }
        }
    }

    // no CTA may exit while peers' multicast writes into its smem are possible
    asm volatile("barrier.cluster.arrive.aligned;" ::: "memory");
    asm volatile("barrier.cluster.wait.aligned;"   ::: "memory");
}

// ---------------- launch ----------------
extern "C" void kernel_launch(void* const* d_in, const int* in_sizes, int n_in,
                              void* d_out, int out_size) {
    const float *x = nullptr, *h = nullptr, *wr = nullptr, *br = nullptr,
                *wo = nullptr, *bo = nullptr;
    for (int i = 0; i < n_in; ++i) {
        switch (in_sizes[i]) {
            case 512 * 128 * 256: x  = (const float*)d_in[i]; break;  // 16777216
            case 128 * 1024:      h  = (const float*)d_in[i]; break;  // 131072
            case 1024 * 1024:     wr = (const float*)d_in[i]; break;  // 1048576
            case 1024:            br = (const float*)d_in[i]; break;
            case 256 * 1024:      wo = (const float*)d_in[i]; break;  // 262144
            case 256:             bo = (const float*)d_in[i]; break;
            default: break;
        }
    }
    cudaFuncSetAttribute(trnn_persistent,
                         cudaFuncAttributeMaxDynamicSharedMemorySize, SMEM_TOTAL);
    trnn_init<<<512, 256>>>(wr, wo, h);
    trnn_persistent<<<NCTAS, NTHREADS, SMEM_TOTAL>>>(x, h, br, bo, (float*)d_out);
}